// round 16
// baseline (speedup 1.0000x reference)
#include <cuda_runtime.h>
#include <cuda_fp16.h>

typedef unsigned int uint;

#define BDIM 4
#define CDIM 512
#define HWD 4096
#define HIDD 256
#define MAXE 16
#define MAXC 256

// ---------------- scratch ----------------
// packed fp16-split: uint = (fp16 hi) | (fp16 lo << 16)
__device__ uint   g_mvnC_t[(size_t)BDIM * HWD * CDIM]; // mvn(content)^T packed [HW,C]
__device__ uint   g_mvnS_t[(size_t)BDIM * HWD * CDIM]; // mvn(style)^T packed [HW,C]
__device__ uint   g_Tt[(size_t)BDIM * HWD * CDIM];     // Tt = (M·mvnS)^T packed [HW,C]
__device__ uint   g_Mm[CDIM * CDIM];                   // M = Wf^T Wg packed
__device__ char   g_qC[(size_t)BDIM * HWD * CDIM];     // int8 mvnC^T (scale 16)
__device__ char   g_qT[(size_t)BDIM * HWD * CDIM];     // int8 Tt (scale 16)
__device__ __half g_S[(size_t)BDIM * HWD * HWD];       // fp16 approx logits
__device__ __half g_styleT[(size_t)BDIM * HWD * CDIM]; // [HW,C] fp16
__device__ __half g_contentT[(size_t)BDIM * HWD * CDIM];
__device__ __half g_styleR[(size_t)BDIM * CDIM * HWD]; // style*rnS [C,HW] fp16
__device__ __half g_Y[(size_t)BDIM * HWD * CDIM];      // gathered style [HW,C] fp16
__device__ __half g_T1t[(size_t)BDIM * HIDD * CDIM];   // [HID,C] fp16
__device__ float  g_hmid[(size_t)BDIM * HWD * HIDD];
__device__ float  g_rnC[BDIM * HWD];
__device__ float  g_rnS[BDIM * HWD];
__device__ float  g_clamp[BDIM * HWD];
__device__ float  g_p[CDIM];
__device__ float  g_u[BDIM * HWD];
__device__ float  g_wb[CDIM];
__device__ float  g_gsum[BDIM * HWD];
__device__ int    g_scnt[BDIM * HWD];
__device__ int    g_sidx[(size_t)BDIM * HWD * MAXE];
__device__ float  g_sval[(size_t)BDIM * HWD * MAXE];
__device__ int    g_ccnt[BDIM * HWD];
__device__ int    g_cidx[(size_t)BDIM * HWD * MAXC];
__device__ float  g_cmx[BDIM * HWD];
__device__ float  g_ctail[BDIM * HWD];
__device__ float2 g_statC[BDIM * CDIM];
__device__ float2 g_statS[BDIM * CDIM];
__device__ uint   g_Wfs[CDIM * CDIM];
__device__ uint   g_Wgs[CDIM * CDIM];
__device__ __half g_WhT[CDIM * CDIM];
__device__ __half g_Wos[CDIM * CDIM];
__device__ __half g_Wouth[CDIM * CDIM];
__device__ __half g_W1h[HIDD * HWD];

// ---------------- helpers ----------------
__device__ __forceinline__ uint packsplit16(float x) {
    __half h = __float2half_rn(x);
    float hf = __half2float(h);
    __half l = __float2half_rn(x - hf);
    return (uint)__half_as_ushort(h) | ((uint)__half_as_ushort(l) << 16);
}
__device__ __forceinline__ float unpack16(uint v) {
    return __half2float(__ushort_as_half((unsigned short)(v & 0xffff))) +
           __half2float(__ushort_as_half((unsigned short)(v >> 16)));
}
__device__ __forceinline__ char quant8(float x) {
    int q = __float2int_rn(x * 16.f);
    q = max(-127, min(127, q));
    return (char)q;
}
__device__ __forceinline__ uint prmtb(uint a, uint b, uint s) {
    uint d;
    asm("prmt.b32 %0,%1,%2,%3;" : "=r"(d) : "r"(a), "r"(b), "r"(s));
    return d;
}
__device__ __forceinline__ void mma_hf(float* d, const uint* a, const uint* b) {
    asm volatile(
        "mma.sync.aligned.m16n8k16.row.col.f32.f16.f16.f32 "
        "{%0,%1,%2,%3},{%4,%5,%6,%7},{%8,%9},{%0,%1,%2,%3};"
        : "+f"(d[0]), "+f"(d[1]), "+f"(d[2]), "+f"(d[3])
        : "r"(a[0]), "r"(a[1]), "r"(a[2]), "r"(a[3]), "r"(b[0]), "r"(b[1]));
}
__device__ __forceinline__ void mma_s8(int* d, const uint* a, const uint* b) {
    asm volatile(
        "mma.sync.aligned.m16n8k32.row.col.s32.s8.s8.s32 "
        "{%0,%1,%2,%3},{%4,%5,%6,%7},{%8,%9},{%0,%1,%2,%3};"
        : "+r"(d[0]), "+r"(d[1]), "+r"(d[2]), "+r"(d[3])
        : "r"(a[0]), "r"(a[1]), "r"(a[2]), "r"(a[3]), "r"(b[0]), "r"(b[1]));
}

// ---------------- elementwise kernels ----------------
__global__ void split16_kernel(const float4* __restrict__ x, uint4* __restrict__ y) {
    int i = blockIdx.x * 256 + threadIdx.x;
    float4 v = x[i];
    y[i] = make_uint4(packsplit16(v.x), packsplit16(v.y), packsplit16(v.z), packsplit16(v.w));
}

__global__ void tohalf_kernel(const float4* __restrict__ x, __half* __restrict__ y) {
    int i = blockIdx.x * 256 + threadIdx.x;
    float4 v = x[i];
    __half2* o = (__half2*)(y + (size_t)i * 4);
    o[0] = __floats2half2_rn(v.x, v.y);
    o[1] = __floats2half2_rn(v.z, v.w);
}

__global__ void scalehalf_kernel(const float* __restrict__ x, const float* __restrict__ rn,
                                 __half* __restrict__ y) {
    int b = blockIdx.y;
    size_t i = (size_t)blockIdx.x * 256 + threadIdx.x;
    size_t base = (size_t)b * CDIM * HWD + i * 4;
    int l = (int)((i * 4) % HWD);
    float4 v = *(const float4*)(x + base);
    float4 r = *(const float4*)(rn + (size_t)b * HWD + l);
    __half2* o = (__half2*)(y + base);
    o[0] = __floats2half2_rn(v.x * r.x, v.y * r.y);
    o[1] = __floats2half2_rn(v.z * r.z, v.w * r.w);
}

__global__ void stats_kernel(const float* __restrict__ x, float2* __restrict__ st) {
    int bc = blockIdx.x;
    const float* px = x + (size_t)bc * HWD;
    int t = threadIdx.x;
    float s = 0.f, s2 = 0.f;
    for (int i = t; i < HWD; i += 256) { float v = px[i]; s += v; s2 += v * v; }
    __shared__ float r1[256], r2[256];
    r1[t] = s; r2[t] = s2; __syncthreads();
    for (int o = 128; o > 0; o >>= 1) { if (t < o) { r1[t] += r1[t + o]; r2[t] += r2[t + o]; } __syncthreads(); }
    if (t == 0) {
        float mean = r1[0] * (1.0f / HWD);
        float var = (r2[0] - (float)HWD * mean * mean) * (1.0f / (HWD - 1));
        st[bc] = make_float2(mean, rsqrtf(var + 1e-5f));
    }
}

// fused: read x tile once -> xT fp16 [HW,C], mvn packed [HW,C], optional int8 [HW,C]
__global__ void fusedT_kernel(const float* __restrict__ x, const float2* __restrict__ st,
                              __half* __restrict__ xT, uint* __restrict__ mvnp,
                              char* __restrict__ q8) {
    __shared__ float tile[32][33];
    int b = blockIdx.z;
    int c0 = blockIdx.y * 32, h0 = blockIdx.x * 32;
    int tx = threadIdx.x, ty = threadIdx.y;
#pragma unroll
    for (int j = 0; j < 4; j++) {
        int c = c0 + ty + j * 8;
        tile[ty + j * 8][tx] = x[((size_t)b * CDIM + c) * HWD + h0 + tx];
    }
    __syncthreads();
    float2 f = st[b * CDIM + c0 + tx];
#pragma unroll
    for (int j = 0; j < 4; j++) {
        int h = h0 + ty + j * 8;
        float v = tile[tx][ty + j * 8];
        float vm = (v - f.x) * f.y;
        xT[((size_t)b * HWD + h) * CDIM + c0 + tx] = __float2half_rn(v);
        mvnp[((size_t)b * HWD + h) * CDIM + c0 + tx] = packsplit16(vm);
        if (q8) q8[((size_t)b * HWD + h) * CDIM + c0 + tx] = quant8(vm);
    }
}

// reciprocal channel-L2 norm from fp16 transpose [HW,C]
__global__ void rnorm_t_kernel(const __half* __restrict__ xt, float* __restrict__ rn) {
    int row = blockIdx.x * 8 + (threadIdx.x >> 5);
    int lane = threadIdx.x & 31;
    const uint4* p = (const uint4*)(xt + (size_t)row * CDIM) + lane;
    float s = 0.f;
#pragma unroll
    for (int i = 0; i < 2; i++) {
        uint4 v = p[i * 32];
        const __half2* h = (const __half2*)&v;
#pragma unroll
        for (int j = 0; j < 4; j++) { float2 f = __half22float2(h[j]); s += f.x * f.x + f.y * f.y; }
    }
#pragma unroll
    for (int o = 16; o > 0; o >>= 1) s += __shfl_xor_sync(0xffffffffu, s, o);
    if (lane == 0) rn[row] = 1.0f / fmaxf(sqrtf(s), 1e-12f);
}

__global__ void trans512_kernel(const float* __restrict__ x, __half* __restrict__ y) {
    __shared__ float tile[32][33];
    int o0 = blockIdx.y * 32, i0 = blockIdx.x * 32;
    int tx = threadIdx.x, ty = threadIdx.y;
#pragma unroll
    for (int j = 0; j < 4; j++)
        tile[ty + j * 8][tx] = x[(size_t)(o0 + ty + j * 8) * CDIM + i0 + tx];
    __syncthreads();
#pragma unroll
    for (int j = 0; j < 4; j++)
        y[(size_t)(i0 + ty + j * 8) * CDIM + o0 + tx] = __float2half_rn(tile[tx][ty + j * 8]);
}

__global__ void p_kernel(const float* __restrict__ Wg, const float* __restrict__ bf,
                         float* __restrict__ p) {
    int c = blockIdx.x * 128 + threadIdx.x;
    float s = 0.f;
    for (int o = 0; o < CDIM; o++) s += bf[o] * Wg[o * CDIM + c];
    p[c] = s;
}

__global__ void wb_kernel(const float* __restrict__ Wout, const float* __restrict__ bh,
                          float* __restrict__ wb) {
    int c = blockIdx.x * 128 + threadIdx.x;
    float s = 0.f;
    for (int o = 0; o < CDIM; o++) s += Wout[(size_t)c * CDIM + o] * bh[o];
    wb[c] = s;
}

// u[row] = sum_c mvnSt[row,c] * p[c]   (warp per row)
__global__ void u_kernel(const uint* __restrict__ mvnSt, const float* __restrict__ p,
                         float* __restrict__ u) {
    int row = blockIdx.x * 8 + (threadIdx.x >> 5);
    int lane = threadIdx.x & 31;
    const uint* px = mvnSt + (size_t)row * CDIM + lane;
    float s = 0.f;
#pragma unroll
    for (int i = 0; i < 16; i++) s += unpack16(px[i * 32]) * p[lane + i * 32];
#pragma unroll
    for (int o = 16; o > 0; o >>= 1) s += __shfl_xor_sync(0xffffffffu, s, o);
    if (lane == 0) u[row] = s;
}

__global__ void psi_kernel(const float* __restrict__ hmid, const float* __restrict__ W2,
                           const float* __restrict__ b2, float* __restrict__ clampv) {
    int row = blockIdx.x * 4 + (threadIdx.x >> 5);
    int lane = threadIdx.x & 31;
    const float* p = hmid + (size_t)row * HIDD;
    float s = 0.f;
#pragma unroll
    for (int j = lane; j < HIDD; j += 32) s += p[j] * W2[j];
#pragma unroll
    for (int o = 16; o > 0; o >>= 1) s += __shfl_xor_sync(0xffffffffu, s, o);
    if (lane == 0) {
        float psi = 1.f / (1.f + __expf(-(s + b2[0])));
        clampv[row] = psi * 0.5f + 0.4f;
    }
}

// candidate pass over approx fp16 logits (Shat + u)
__global__ void cand_kernel(const __half* __restrict__ S, const float* __restrict__ uvec,
                            int* __restrict__ ccnt, int* __restrict__ cidx,
                            float* __restrict__ cmx, float* __restrict__ ctail) {
    size_t row = blockIdx.x;
    int b = (int)(row >> 12);
    const __half* p = S + row * HWD;
    const float* ub = uvec + (size_t)b * HWD;
    __shared__ float buf[HWD];
    __shared__ float red[256];
    int t = threadIdx.x;
    float mx = -1e30f;
    for (int i = t; i < HWD; i += 256) {
        float v = __half2float(p[i]) + ub[i];
        buf[i] = v; mx = fmaxf(mx, v);
    }
    red[t] = mx; __syncthreads();
    for (int o = 128; o > 0; o >>= 1) { if (t < o) red[t] = fmaxf(red[t], red[t + o]); __syncthreads(); }
    mx = red[0]; __syncthreads();
    float sum = 0.f;
    for (int i = t; i < HWD; i += 256) sum += __expf(buf[i] - mx);
    red[t] = sum; __syncthreads();
    for (int o = 128; o > 0; o >>= 1) { if (t < o) red[t] += red[t + o]; __syncthreads(); }
    float total = red[0];
    float thr = mx - 13.0f;
    if (t < 32) {
        int cnt = 0;
        float cap = 0.f;
        for (int i0 = 0; i0 < HWD; i0 += 32) {
            float v = buf[i0 + t];
            bool q = v > thr;
            uint m = __ballot_sync(0xffffffffu, q);
            if (q) {
                int pos = cnt + __popc(m & ((1u << t) - 1u));
                if (pos < MAXC) {
                    cidx[row * MAXC + pos] = i0 + t;
                    cap += __expf(v - mx);
                }
            }
            cnt += __popc(m);
        }
#pragma unroll
        for (int o = 16; o > 0; o >>= 1) cap += __shfl_xor_sync(0xffffffffu, cap, o);
        if (t == 0) {
            ccnt[row] = cnt < MAXC ? cnt : MAXC;
            cmx[row] = mx;
            ctail[row] = fmaxf(total - cap, 0.f);
        }
    }
}

// exact pass: recompute candidate logits in fp32 (warp-per-candidate)
__global__ void exact_kernel(const uint* __restrict__ mvnCt, const uint* __restrict__ Tt,
                             const float* __restrict__ uvec, const float* __restrict__ clampv,
                             const int* __restrict__ ccnt, const int* __restrict__ cidx,
                             const float* __restrict__ cmx, const float* __restrict__ ctail,
                             int* __restrict__ scnt, int* __restrict__ sidx,
                             float* __restrict__ sval) {
    int row = blockIdx.x;
    int b = row >> 12;
    int t = threadIdx.x;   // 128
    int lane = t & 31, w = t >> 5;
    __shared__ float arow[CDIM];
    __shared__ float elog[MAXC];
    const uint* ar = mvnCt + (size_t)row * CDIM;
#pragma unroll
    for (int q = 0; q < 4; q++) arow[t + 128 * q] = unpack16(ar[t + 128 * q]);
    __syncthreads();
    int cnt = ccnt[row];
    for (int j = w; j < cnt; j += 4) {
        int l = cidx[row * MAXC + j];
        const uint* tc = Tt + (size_t)b * HWD * CDIM + (size_t)l * CDIM;
        float s = 0.f;
#pragma unroll
        for (int q = 0; q < 16; q++) s += arow[lane + 32 * q] * unpack16(tc[lane + 32 * q]);
#pragma unroll
        for (int o = 16; o > 0; o >>= 1) s += __shfl_xor_sync(0xffffffffu, s, o);
        if (lane == 0) elog[j] = s + uvec[(size_t)b * HWD + l];
    }
    __syncthreads();
    if (t == 0) {
        float mx = cmx[row];
        float sum = ctail[row];
        for (int j = 0; j < cnt; j++) sum += __expf(elog[j] - mx);
        float inv = 1.0f / sum;
        float cv = clampv[row];
        int k = 0;
        for (int j = 0; j < cnt; j++) {
            float Sv = __expf(elog[j] - mx) * inv;
            float d = Sv - cv;
            if (d > -0.3f && k < MAXE) {
                sidx[row * MAXE + k] = cidx[row * MAXC + j];
                sval[row * MAXE + k] = 1.0f / (1.0f + __expf(-50.0f * d));
                k++;
            }
        }
        scnt[row] = k;
    }
}

// Y[row,c] = sum_j g_j * styleT[l_j, c];  gsum[row] = sum_j g_j
__global__ void gatherY_kernel(const __half* __restrict__ styleT, const int* __restrict__ scnt,
                               const int* __restrict__ sidx, const float* __restrict__ sval,
                               __half* __restrict__ Y, float* __restrict__ gsum) {
    int row = blockIdx.x;
    int b = row >> 12;
    int t = threadIdx.x;
    int c = t * 4;
    const __half* base = styleT + (size_t)b * HWD * CDIM + c;
    float a0 = 0.f, a1 = 0.f, a2 = 0.f, a3 = 0.f;
    float gs = 0.f;
    int cnt = scnt[row];
    for (int j = 0; j < cnt; j++) {
        int l = sidx[row * MAXE + j];
        float g = sval[row * MAXE + j];
        gs += g;
        uint2 v = *(const uint2*)(base + (size_t)l * CDIM);
        float2 f0 = __half22float2(*(__half2*)&v.x);
        float2 f1 = __half22float2(*(__half2*)&v.y);
        a0 += g * f0.x; a1 += g * f0.y; a2 += g * f1.x; a3 += g * f1.y;
    }
    uint2 o;
    *(__half2*)&o.x = __floats2half2_rn(a0, a1);
    *(__half2*)&o.y = __floats2half2_rn(a2, a3);
    *(uint2*)(Y + (size_t)row * CDIM + c) = o;
    if (t == 0) gsum[row] = gs;
}

// ---------------- shared tile movers (packed uint operands) ----------------
template <bool KM>
__device__ __forceinline__ void ldg_tile(const uint* __restrict__ P, int ld, int k0, int c0,
                                         uint4 (&r)[2], int t) {
#pragma unroll
    for (int i = 0; i < 2; i++) {
        int f = i * 256 + t;
        if (KM) {
            int kk = f >> 5, cc = (f & 31) << 2;
            r[i] = *(const uint4*)(P + (size_t)(k0 + kk) * ld + c0 + cc);
        } else {
            int cc = f >> 2, kk = (f & 3) << 2;
            r[i] = *(const uint4*)(P + (size_t)(c0 + cc) * ld + k0 + kk);
        }
    }
}
template <bool KM, bool SPLIT>
__device__ __forceinline__ void sts_tile(unsigned short* hi, unsigned short* lo,
                                         const uint4 (&r)[2], int t) {
#pragma unroll
    for (int i = 0; i < 2; i++) {
        int f = i * 256 + t;
        uint w0 = r[i].x, w1 = r[i].y, w2 = r[i].z, w3 = r[i].w;
        if (KM) {
            int kk = f >> 5, cc = (f & 31) << 2;
            hi[(cc + 0) * 24 + kk] = (unsigned short)w0;
            hi[(cc + 1) * 24 + kk] = (unsigned short)w1;
            hi[(cc + 2) * 24 + kk] = (unsigned short)w2;
            hi[(cc + 3) * 24 + kk] = (unsigned short)w3;
            if (SPLIT) {
                lo[(cc + 0) * 24 + kk] = (unsigned short)(w0 >> 16);
                lo[(cc + 1) * 24 + kk] = (unsigned short)(w1 >> 16);
                lo[(cc + 2) * 24 + kk] = (unsigned short)(w2 >> 16);
                lo[(cc + 3) * 24 + kk] = (unsigned short)(w3 >> 16);
            }
        } else {
            int cc = f >> 2, kk = (f & 3) << 2;
            *(uint*)(hi + cc * 24 + kk)     = prmtb(w0, w1, 0x5410);
            *(uint*)(hi + cc * 24 + kk + 2) = prmtb(w2, w3, 0x5410);
            if (SPLIT) {
                *(uint*)(lo + cc * 24 + kk)     = prmtb(w0, w1, 0x7632);
                *(uint*)(lo + cc * 24 + kk + 2) = prmtb(w2, w3, 0x7632);
            }
        }
    }
}

// ---------------- fp16-split GEMM (fp32 accum; Mm/Tt; optional int8 side-output) ----
template <bool A_KM, bool B_NK, bool SPLIT>
__global__ __launch_bounds__(256)
void tc_gemm(const uint* __restrict__ A, const uint* __restrict__ B, float* __restrict__ C,
             int K, int lda, int ldb, int ldc,
             long long sA, long long sB, long long sC,
             const float* __restrict__ bias, long long sBias, int biasMode, int outMode,
             char* __restrict__ C8) {
    __shared__ unsigned short AsH[2][128 * 24];
    __shared__ unsigned short BsH[2][128 * 24];
    __shared__ unsigned short AsL[2][SPLIT ? 128 * 24 : 8];
    __shared__ unsigned short BsL[2][SPLIT ? 128 * 24 : 8];
    int bz = blockIdx.z;
    A += sA * bz; B += sB * bz;
    float* Cb = C + sC * bz;
    char* Cb8 = C8 ? C8 + sC * bz : nullptr;
    int bm = blockIdx.y * 128, bn = blockIdx.x * 128;
    int t = threadIdx.x, w = t >> 5, lane = t & 31;
    int wm = (w >> 1) * 32, wn = (w & 1) * 64;
    int g = lane >> 2, tg = lane & 3;

    float acc[2][8][4];
#pragma unroll
    for (int mi = 0; mi < 2; mi++)
#pragma unroll
        for (int ni = 0; ni < 8; ni++)
#pragma unroll
            for (int r = 0; r < 4; r++) acc[mi][ni][r] = 0.f;

    uint4 rA[2], rB[2];
    ldg_tile<A_KM>(A, lda, 0, bm, rA, t);
    ldg_tile<!B_NK>(B, ldb, 0, bn, rB, t);
    sts_tile<A_KM, SPLIT>(AsH[0], AsL[0], rA, t);
    sts_tile<!B_NK, SPLIT>(BsH[0], BsL[0], rB, t);
    __syncthreads();

    int T = K / 16, p = 0;
    for (int kt = 0; kt < T; kt++) {
        if (kt + 1 < T) {
            ldg_tile<A_KM>(A, lda, (kt + 1) * 16, bm, rA, t);
            ldg_tile<!B_NK>(B, ldb, (kt + 1) * 16, bn, rB, t);
        }
        uint aH[2][4], aL[2][4], bH[8][2], bL[8][2];
#pragma unroll
        for (int mi = 0; mi < 2; mi++) {
            const unsigned short* pH = AsH[p] + (wm + mi * 16 + g) * 24 + 2 * tg;
            aH[mi][0] = *(const uint*)(pH);      aH[mi][1] = *(const uint*)(pH + 8 * 24);
            aH[mi][2] = *(const uint*)(pH + 8);  aH[mi][3] = *(const uint*)(pH + 8 * 24 + 8);
            if (SPLIT) {
                const unsigned short* pL = AsL[p] + (wm + mi * 16 + g) * 24 + 2 * tg;
                aL[mi][0] = *(const uint*)(pL);      aL[mi][1] = *(const uint*)(pL + 8 * 24);
                aL[mi][2] = *(const uint*)(pL + 8);  aL[mi][3] = *(const uint*)(pL + 8 * 24 + 8);
            }
        }
#pragma unroll
        for (int ni = 0; ni < 8; ni++) {
            const unsigned short* pH = BsH[p] + (wn + ni * 8 + g) * 24 + 2 * tg;
            bH[ni][0] = *(const uint*)(pH); bH[ni][1] = *(const uint*)(pH + 8);
            if (SPLIT) {
                const unsigned short* pL = BsL[p] + (wn + ni * 8 + g) * 24 + 2 * tg;
                bL[ni][0] = *(const uint*)(pL); bL[ni][1] = *(const uint*)(pL + 8);
            }
        }
#pragma unroll
        for (int mi = 0; mi < 2; mi++)
#pragma unroll
            for (int ni = 0; ni < 8; ni++) {
                mma_hf(acc[mi][ni], aH[mi], bH[ni]);
                if (SPLIT) {
                    mma_hf(acc[mi][ni], aH[mi], bL[ni]);
                    mma_hf(acc[mi][ni], aL[mi], bH[ni]);
                }
            }
        if (kt + 1 < T) {
            p ^= 1;
            sts_tile<A_KM, SPLIT>(AsH[p], AsL[p], rA, t);
            sts_tile<!B_NK, SPLIT>(BsH[p], BsL[p], rB, t);
            __syncthreads();
        }
    }

#pragma unroll
    for (int mi = 0; mi < 2; mi++) {
#pragma unroll
        for (int ni = 0; ni < 8; ni++) {
#pragma unroll
            for (int hf = 0; hf < 2; hf++) {
                int m = bm + wm + mi * 16 + g + hf * 8;
                int n = bn + wn + ni * 8 + 2 * tg;
                float v0 = acc[mi][ni][hf * 2 + 0];
                float v1 = acc[mi][ni][hf * 2 + 1];
                if (biasMode == 1) { float b = bias[m]; v0 += b; v1 += b; }
                if (biasMode == 2) { v0 += bias[sBias * bz + n]; v1 += bias[sBias * bz + n + 1]; }
                if (outMode == 0) {
                    *(float2*)(Cb + (size_t)m * ldc + n) = make_float2(v0, v1);
                } else {
                    uint2 ov = make_uint2(packsplit16(v0), packsplit16(v1));
                    *(uint2*)((uint*)Cb + (size_t)m * ldc + n) = ov;
                    if (Cb8) {
                        unsigned short qq = (unsigned short)(unsigned char)quant8(v0) |
                                            ((unsigned short)(unsigned char)quant8(v1) << 8);
                        *(unsigned short*)(Cb8 + (size_t)m * ldc + n) = qq;
                    }
                }
            }
        }
    }
}

// ---------------- approx S GEMM: int8 (scale 16x16 -> /256), fp16 out ----------------
// D[m,n] = (1/256) * sum_k qA[m,k]*qB[n,k];  A = qC [HW,C], B = qT [HW,C]
__device__ __forceinline__ void ldst8(const char* __restrict__ G, int ld, int row0, int k0,
                                      char* __restrict__ Sm, int t) {
    int row = t >> 1, off = (t & 1) * 16;
    uint4 v = *(const uint4*)(G + (size_t)(row0 + row) * ld + k0 + off);
    *(uint4*)(Sm + row * 48 + off) = v;
}

__global__ __launch_bounds__(256)
void sgemm_s8(const char* __restrict__ A, const char* __restrict__ B, __half* __restrict__ C,
              int K, int lda, int ldb, int ldc,
              long long sA, long long sB, long long sC) {
    __shared__ char As[2][128 * 48];
    __shared__ char Bs[2][128 * 48];
    int bz = blockIdx.z;
    A += sA * bz; B += sB * bz;
    __half* Cb = C + sC * bz;
    int bm = blockIdx.y * 128, bn = blockIdx.x * 128;
    int t = threadIdx.x, w = t >> 5, lane = t & 31;
    int wm = (w >> 1) * 32, wn = (w & 1) * 64;
    int g = lane >> 2, tg = lane & 3;

    int acc[2][8][4];
#pragma unroll
    for (int mi = 0; mi < 2; mi++)
#pragma unroll
        for (int ni = 0; ni < 8; ni++)
#pragma unroll
            for (int r = 0; r < 4; r++) acc[mi][ni][r] = 0;

    ldst8(A, lda, bm, 0, As[0], t);
    ldst8(B, ldb, bn, 0, Bs[0], t);
    __syncthreads();

    int T = K / 32, p = 0;
    for (int kt = 0; kt < T; kt++) {
        uint4 rA, rB;
        if (kt + 1 < T) {
            int row = t >> 1, off = (t & 1) * 16;
            rA = *(const uint4*)(A + (size_t)(bm + row) * lda + (kt + 1) * 32 + off);
            rB = *(const uint4*)(B + (size_t)(bn + row) * ldb + (kt + 1) * 32 + off);
        }
        uint a[2][4], b[8][2];
#pragma unroll
        for (int mi = 0; mi < 2; mi++) {
            const char* pA = As[p] + (wm + mi * 16 + g) * 48 + 4 * tg;
            a[mi][0] = *(const uint*)(pA);
            a[mi][1] = *(const uint*)(pA + 8 * 48);
            a[mi][2] = *(const uint*)(pA + 16);
            a[mi][3] = *(const uint*)(pA + 8 * 48 + 16);
        }
#pragma unroll
        for (int ni = 0; ni < 8; ni++) {
            const char* pB = Bs[p] + (wn + ni * 8 + g) * 48 + 4 * tg;
            b[ni][0] = *(const uint*)(pB);
            b[ni][1] = *(const uint*)(pB + 16);
        }
#pragma unroll
        for (int mi = 0; mi < 2; mi++)
#pragma unroll
            for (int ni = 0; ni < 8; ni++)
                mma_s8(acc[mi][ni], a[mi], b[ni]);
        if (kt + 1 < T) {
            p ^= 1;
            int row = t >> 1, off = (t & 1) * 16;
            *(uint4*)(As[p] + row * 48 + off) = rA;
            *(uint4*)(Bs[p] + row * 48 + off) = rB;
            __syncthreads();
        }
    }

    const float sc = 1.0f / 256.0f;
#pragma unroll
    for (int mi = 0; mi < 2; mi++) {
#pragma unroll
        for (int ni = 0; ni < 8; ni++) {
#pragma unroll
            for (int hf = 0; hf < 2; hf++) {
                int m = bm + wm + mi * 16 + g + hf * 8;
                int n = bn + wn + ni * 8 + 2 * tg;
                float v0 = (float)acc[mi][ni][hf * 2 + 0] * sc;
                float v1 = (float)acc[mi][ni][hf * 2 + 1] * sc;
                *(__half2*)(Cb + (size_t)m * ldc + n) = __floats2half2_rn(v0, v1);
            }
        }
    }
}

// ---------------- plain fp16 GEMM with register prefetch + rank-1 epilogue ----------------
__device__ __forceinline__ uint4 ldg16(const __half* __restrict__ G, size_t ld, int row0, int k0, int t) {
    int row = t >> 1, q = (t & 1) * 8;
    return *(const uint4*)(G + (size_t)(row0 + row) * ld + k0 + q);
}
__device__ __forceinline__ void sts16(__half* __restrict__ Sm, uint4 v, int t) {
    int row = t >> 1, q = (t & 1) * 8;
    *(uint4*)(Sm + row * 24 + q) = v;
}

__global__ __launch_bounds__(256)
void hgemm(const __half* __restrict__ A, const __half* __restrict__ B, float* __restrict__ C,
           int K, size_t lda, size_t ldb, int ldc,
           long long sA, long long sB, long long sC,
           const float* __restrict__ bias, int biasMode,
           const float* __restrict__ scaleM, long long sSM,
           const float* __restrict__ vecM,
           const float* __restrict__ vecN, long long sVN,
           const float* __restrict__ addSrc, long long sAdd,
           int actMode, int outMode) {
    __shared__ __half As[2][128 * 24];
    __shared__ __half Bs[2][128 * 24];
    int bz = blockIdx.z;
    A += sA * bz; B += sB * bz;
    float*  CbF = C + sC * bz;
    __half* CbH = (__half*)C + sC * bz;
    int bm = blockIdx.y * 128, bn = blockIdx.x * 128;
    int t = threadIdx.x, w = t >> 5, lane = t & 31;
    int wm = (w >> 1) * 32, wn = (w & 1) * 64;
    int g = lane >> 2, tg = lane & 3;

    float acc[2][8][4];
#pragma unroll
    for (int mi = 0; mi < 2; mi++)
#pragma unroll
        for (int ni = 0; ni < 8; ni++)
#pragma unroll
            for (int r = 0; r < 4; r++) acc[mi][ni][r] = 0.f;

    uint4 rA = ldg16(A, lda, bm, 0, t);
    uint4 rB = ldg16(B, ldb, bn, 0, t);
    sts16(As[0], rA, t);
    sts16(Bs[0], rB, t);
    __syncthreads();

    int T = K / 16, p = 0;
    for (int kt = 0; kt < T; kt++) {
        if (kt + 1 < T) {
            rA = ldg16(A, lda, bm, (kt + 1) * 16, t);
            rB = ldg16(B, ldb, bn, (kt + 1) * 16, t);
        }
        uint a[2][4], b[8][2];
#pragma unroll
        for (int mi = 0; mi < 2; mi++) {
            const __half* pA = As[p] + (wm + mi * 16 + g) * 24 + 2 * tg;
            a[mi][0] = *(const uint*)(pA);      a[mi][1] = *(const uint*)(pA + 8 * 24);
            a[mi][2] = *(const uint*)(pA + 8);  a[mi][3] = *(const uint*)(pA + 8 * 24 + 8);
        }
#pragma unroll
        for (int ni = 0; ni < 8; ni++) {
            const __half* pB = Bs[p] + (wn + ni * 8 + g) * 24 + 2 * tg;
            b[ni][0] = *(const uint*)(pB); b[ni][1] = *(const uint*)(pB + 8);
        }
#pragma unroll
        for (int mi = 0; mi < 2; mi++)
#pragma unroll
            for (int ni = 0; ni < 8; ni++)
                mma_hf(acc[mi][ni], a[mi], b[ni]);
        if (kt + 1 < T) {
            p ^= 1;
            sts16(As[p], rA, t);
            sts16(Bs[p], rB, t);
            __syncthreads();
        }
    }

#pragma unroll
    for (int mi = 0; mi < 2; mi++) {
#pragma unroll
        for (int ni = 0; ni < 8; ni++) {
#pragma unroll
            for (int hf = 0; hf < 2; hf++) {
                int m = bm + wm + mi * 16 + g + hf * 8;
                int n = bn + wn + ni * 8 + 2 * tg;
                float v0 = acc[mi][ni][hf * 2 + 0];
                float v1 = acc[mi][ni][hf * 2 + 1];
                if (scaleM) { float s = scaleM[sSM * bz + m]; v0 *= s; v1 *= s; }
                if (biasMode == 1) { float b_ = bias[m]; v0 += b_; v1 += b_; }
                if (biasMode == 2) { v0 += bias[n]; v1 += bias[n + 1]; }
                if (vecM) {
                    float vm = vecM[m];
                    v0 += vm * vecN[sVN * bz + n];
                    v1 += vm * vecN[sVN * bz + n + 1];
                }
                if (actMode == 1) {
                    v0 = (v0 > 0.f) ? v0 : 0.2f * v0;
                    v1 = (v1 > 0.f) ? v1 : 0.2f * v1;
                }
                if (addSrc) {
                    v0 += addSrc[sAdd * bz + (size_t)m * ldc + n];
                    v1 += addSrc[sAdd * bz + (size_t)m * ldc + n + 1];
                }
                if (outMode == 0) {
                    *(float2*)(CbF + (size_t)m * ldc + n) = make_float2(v0, v1);
                } else {
                    *(__half2*)(CbH + (size_t)m * ldc + n) = __floats2half2_rn(v0, v1);
                }
            }
        }
    }
}

// ---------------- host launcher ----------------
extern "C" void kernel_launch(void* const* d_in, const int* in_sizes, int n_in,
                              void* d_out, int out_size) {
    const float* content = (const float*)d_in[0];
    const float* style   = (const float*)d_in[1];
    const float* Wf   = (const float*)d_in[2];
    const float* bf   = (const float*)d_in[3];
    const float* Wg   = (const float*)d_in[4];
    const float* bg   = (const float*)d_in[5];
    const float* Wh   = (const float*)d_in[6];
    const float* bh   = (const float*)d_in[7];
    const float* Wout = (const float*)d_in[8];
    const float* bout = (const float*)d_in[9];
    const float* W1   = (const float*)d_in[10];
    const float* b1   = (const float*)d_in[11];
    const float* W2   = (const float*)d_in[12];
    const float* b2   = (const float*)d_in[13];
    float* out = (float*)d_out;

    uint *mvnCt, *mvnSt, *Tt, *Mm, *Wfs, *Wgs;
    char *qC, *qT;
    __half *S, *styleT, *contentT, *styleR, *Yh, *T1t, *WhT, *Wos, *Wouth, *W1h;
    float *hmid, *rnC, *rnS, *clampv, *sval, *pv, *uv, *wbv, *gsum, *cmx, *ctail;
    float2 *stC, *stS;
    int *scnt, *sidx, *ccnt, *cidx;
    cudaGetSymbolAddress((void**)&mvnCt, g_mvnC_t);
    cudaGetSymbolAddress((void**)&mvnSt, g_mvnS_t);
    cudaGetSymbolAddress((void**)&Tt, g_Tt);
    cudaGetSymbolAddress((void**)&Mm, g_Mm);
    cudaGetSymbolAddress((void**)&qC, g_qC);
    cudaGetSymbolAddress((void**)&qT, g_qT);
    cudaGetSymbolAddress((void**)&S, g_S);
    cudaGetSymbolAddress((void**)&styleT, g_styleT);
    cudaGetSymbolAddress((void**)&contentT, g_contentT);
    cudaGetSymbolAddress((void**)&styleR, g_styleR);
    cudaGetSymbolAddress((void**)&Yh, g_Y);
    cudaGetSymbolAddress((void**)&T1t, g_T1t);
    cudaGetSymbolAddress((void**)&hmid, g_hmid);
    cudaGetSymbolAddress((void**)&rnC, g_rnC);
    cudaGetSymbolAddress((void**)&rnS, g_rnS);
    cudaGetSymbolAddress((void**)&clampv, g_clamp);
    cudaGetSymbolAddress((void**)&pv, g_p);
    cudaGetSymbolAddress((void**)&uv, g_u);
    cudaGetSymbolAddress((void**)&wbv, g_wb);
    cudaGetSymbolAddress((void**)&gsum, g_gsum);
    cudaGetSymbolAddress((void**)&scnt, g_scnt);
    cudaGetSymbolAddress((void**)&sidx, g_sidx);
    cudaGetSymbolAddress((void**)&sval, g_sval);
    cudaGetSymbolAddress((void**)&ccnt, g_ccnt);
    cudaGetSymbolAddress((void**)&cidx, g_cidx);
    cudaGetSymbolAddress((void**)&cmx, g_cmx);
    cudaGetSymbolAddress((void**)&ctail, g_ctail);
    cudaGetSymbolAddress((void**)&stC, g_statC);
    cudaGetSymbolAddress((void**)&stS, g_statS);
    cudaGetSymbolAddress((void**)&Wfs, g_Wfs);
    cudaGetSymbolAddress((void**)&Wgs, g_Wgs);
    cudaGetSymbolAddress((void**)&WhT, g_WhT);
    cudaGetSymbolAddress((void**)&Wos, g_Wos);
    cudaGetSymbolAddress((void**)&Wouth, g_Wouth);
    cudaGetSymbolAddress((void**)&W1h, g_W1h);

    const long long CS  = (long long)CDIM * HWD;
    const long long CT  = (long long)HWD * CDIM;
    const long long SS  = (long long)HWD * HWD;
    const long long HSC = (long long)HIDD * CDIM;
    const long long HM  = (long long)HWD * HIDD;

    // 0) weights
    split16_kernel<<<CDIM * CDIM / 1024, 256>>>((const float4*)Wf, (uint4*)Wfs);
    split16_kernel<<<CDIM * CDIM / 1024, 256>>>((const float4*)Wg, (uint4*)Wgs);
    tohalf_kernel<<<CDIM * CDIM / 1024, 256>>>((const float4*)Wout, Wos);
    tohalf_kernel<<<HIDD * HWD / 1024, 256>>>((const float4*)W1, W1h);
    trans512_kernel<<<dim3(16, 16), dim3(32, 8)>>>(Wh, WhT);
    wb_kernel<<<CDIM / 128, 128>>>(Wout, bh, wbv);
    dim3 gW(CDIM / 128, CDIM / 128, 1);
    hgemm<<<gW, 256>>>(Wos, WhT, (float*)Wouth, CDIM, CDIM, CDIM, CDIM,
        0, 0, 0, nullptr, 0, nullptr, 0, nullptr, nullptr, 0, nullptr, 0, 0, 1);

    // 1) stats + fused transpose/mvn(+int8) + norms
    stats_kernel<<<BDIM * CDIM, 256>>>(content, stC);
    stats_kernel<<<BDIM * CDIM, 256>>>(style, stS);
    dim3 gT(HWD / 32, CDIM / 32, BDIM), bT(32, 8);
    fusedT_kernel<<<gT, bT>>>(content, stC, contentT, mvnCt, qC);
    fusedT_kernel<<<gT, bT>>>(style, stS, styleT, mvnSt, nullptr);
    rnorm_t_kernel<<<BDIM * HWD / 8, 256>>>(contentT, rnC);
    rnorm_t_kernel<<<BDIM * HWD / 8, 256>>>(styleT, rnS);
    scalehalf_kernel<<<dim3(CDIM * HWD / 1024, BDIM), 256>>>(style, rnS, styleR);
    p_kernel<<<CDIM / 128, 128>>>(Wg, bf, pv);
    u_kernel<<<BDIM * HWD / 8, 256>>>(mvnSt, pv, uv);

    // 2) logit chain: Mm (split), Tt (split, + int8 qT), approx S (int8)
    dim3 gM(CDIM / 128, CDIM / 128, 1);
    tc_gemm<true, false, true><<<gM, 256>>>(Wfs, Wgs, (float*)Mm, CDIM, CDIM, CDIM, CDIM,
        0, 0, 0, nullptr, 0, 0, 1, nullptr);
    dim3 gTt(CDIM / 128, HWD / 128, BDIM);
    tc_gemm<false, true, true><<<gTt, 256>>>(mvnSt, Mm, (float*)Tt, CDIM, CDIM, CDIM, CDIM,
        CT, 0, CT, nullptr, 0, 0, 1, qT);
    dim3 gBig(HWD / 128, HWD / 128, BDIM);
    sgemm_s8<<<gBig, 256>>>(qC, qT, S, CDIM, CDIM, CDIM, HWD, CT, CT, SS);

    // 3) fused clamp path
    dim3 gT1(CDIM / 128, HIDD / 128, BDIM);
    hgemm<<<gT1, 256>>>(W1h, styleR, (float*)T1t, HWD, HWD, HWD, CDIM,
        0, CS, HSC, nullptr, 0, nullptr, 0, nullptr, nullptr, 0, nullptr, 0, 0, 1);
    dim3 gT2(HIDD / 128, HWD / 128, BDIM);
    hgemm<<<gT2, 256>>>(contentT, T1t, hmid, CDIM, CDIM, CDIM, HIDD,
        CT, HSC, HM, b1, 2, rnC, HWD, nullptr, nullptr, 0, nullptr, 0, 1, 0);
    psi_kernel<<<BDIM * HWD / 4, 128>>>(hmid, W2, b2, clampv);

    // 4) candidates from approx fp16 logits, exact recompute + gate
    cand_kernel<<<BDIM * HWD, 256>>>(S, uv, ccnt, cidx, cmx, ctail);
    exact_kernel<<<BDIM * HWD, 128>>>(mvnCt, Tt, uv, clampv, ccnt, cidx, cmx, ctail,
                                      scnt, sidx, sval);

    // 5) sparse gather + fused output GEMM
    gatherY_kernel<<<BDIM * HWD, 128>>>(styleT, scnt, sidx, sval, Yh, gsum);
    dim3 gF(HWD / 128, CDIM / 128, BDIM);
    hgemm<<<gF, 256>>>(Wouth, Yh, out, CDIM, CDIM, CDIM, HWD,
        0, CT, CS, bout, 1, nullptr, 0, wbv, gsum, HWD, content, CS, 0, 0);
}

// round 17
// speedup vs baseline: 1.1492x; 1.1492x over previous
#include <cuda_runtime.h>
#include <cuda_fp16.h>

typedef unsigned int uint;

#define BDIM 4
#define CDIM 512
#define HWD 4096
#define HIDD 256
#define MAXE 16
#define MAXC 256

// ---------------- scratch ----------------
// packed fp16-split: uint = (fp16 hi) | (fp16 lo << 16)
__device__ uint   g_mvnC_t[(size_t)BDIM * HWD * CDIM]; // mvn(content)^T packed [HW,C]
__device__ uint   g_mvnS_t[(size_t)BDIM * HWD * CDIM]; // mvn(style)^T packed [HW,C]
__device__ uint   g_Tt[(size_t)BDIM * HWD * CDIM];     // Tt = (M·mvnS)^T packed [HW,C]
__device__ uint   g_Mm[CDIM * CDIM];                   // M = Wf^T Wg packed
__device__ __half g_S[(size_t)BDIM * HWD * HWD];       // fp16 approx logits
__device__ __half g_styleT[(size_t)BDIM * HWD * CDIM]; // [HW,C] fp16
__device__ __half g_contentT[(size_t)BDIM * HWD * CDIM];
__device__ __half g_styleR[(size_t)BDIM * CDIM * HWD]; // style*rnS [C,HW] fp16
__device__ __half g_Y[(size_t)BDIM * HWD * CDIM];      // gathered style [HW,C] fp16
__device__ __half g_T1t[(size_t)BDIM * HIDD * CDIM];   // [HID,C] fp16
__device__ float  g_hmid[(size_t)BDIM * HWD * HIDD];
__device__ float  g_rnC[BDIM * HWD];
__device__ float  g_rnS[BDIM * HWD];
__device__ float  g_clamp[BDIM * HWD];
__device__ float  g_p[CDIM];
__device__ float  g_u[BDIM * HWD];
__device__ float  g_wb[CDIM];
__device__ float  g_gsum[BDIM * HWD];
__device__ int    g_scnt[BDIM * HWD];
__device__ int    g_sidx[(size_t)BDIM * HWD * MAXE];
__device__ float  g_sval[(size_t)BDIM * HWD * MAXE];
__device__ int    g_ccnt[BDIM * HWD];
__device__ int    g_cidx[(size_t)BDIM * HWD * MAXC];
__device__ float  g_cmx[BDIM * HWD];
__device__ float2 g_statC[BDIM * CDIM];
__device__ float2 g_statS[BDIM * CDIM];
__device__ uint   g_Wfs[CDIM * CDIM];
__device__ uint   g_Wgs[CDIM * CDIM];
__device__ __half g_WhT[CDIM * CDIM];
__device__ __half g_Wos[CDIM * CDIM];
__device__ __half g_Wouth[CDIM * CDIM];
__device__ __half g_W1h[HIDD * HWD];

// ---------------- helpers ----------------
__device__ __forceinline__ uint packsplit16(float x) {
    __half h = __float2half_rn(x);
    float hf = __half2float(h);
    __half l = __float2half_rn(x - hf);
    return (uint)__half_as_ushort(h) | ((uint)__half_as_ushort(l) << 16);
}
__device__ __forceinline__ float unpack16(uint v) {
    return __half2float(__ushort_as_half((unsigned short)(v & 0xffff))) +
           __half2float(__ushort_as_half((unsigned short)(v >> 16)));
}
__device__ __forceinline__ uint prmtb(uint a, uint b, uint s) {
    uint d;
    asm("prmt.b32 %0,%1,%2,%3;" : "=r"(d) : "r"(a), "r"(b), "r"(s));
    return d;
}
__device__ __forceinline__ void mma_hf(float* d, const uint* a, const uint* b) {
    asm volatile(
        "mma.sync.aligned.m16n8k16.row.col.f32.f16.f16.f32 "
        "{%0,%1,%2,%3},{%4,%5,%6,%7},{%8,%9},{%0,%1,%2,%3};"
        : "+f"(d[0]), "+f"(d[1]), "+f"(d[2]), "+f"(d[3])
        : "r"(a[0]), "r"(a[1]), "r"(a[2]), "r"(a[3]), "r"(b[0]), "r"(b[1]));
}
// fp16 accumulators (approx logits only)
__device__ __forceinline__ void mma_hh(uint* d, const uint* a, const uint* b) {
    asm volatile(
        "mma.sync.aligned.m16n8k16.row.col.f16.f16.f16.f16 "
        "{%0,%1},{%2,%3,%4,%5},{%6,%7},{%0,%1};"
        : "+r"(d[0]), "+r"(d[1])
        : "r"(a[0]), "r"(a[1]), "r"(a[2]), "r"(a[3]), "r"(b[0]), "r"(b[1]));
}

// ---------------- elementwise kernels ----------------
__global__ void split16_kernel(const float4* __restrict__ x, uint4* __restrict__ y) {
    int i = blockIdx.x * 256 + threadIdx.x;
    float4 v = x[i];
    y[i] = make_uint4(packsplit16(v.x), packsplit16(v.y), packsplit16(v.z), packsplit16(v.w));
}

__global__ void tohalf_kernel(const float4* __restrict__ x, __half* __restrict__ y) {
    int i = blockIdx.x * 256 + threadIdx.x;
    float4 v = x[i];
    __half2* o = (__half2*)(y + (size_t)i * 4);
    o[0] = __floats2half2_rn(v.x, v.y);
    o[1] = __floats2half2_rn(v.z, v.w);
}

__global__ void scalehalf_kernel(const float* __restrict__ x, const float* __restrict__ rn,
                                 __half* __restrict__ y) {
    int b = blockIdx.y;
    size_t i = (size_t)blockIdx.x * 256 + threadIdx.x;
    size_t base = (size_t)b * CDIM * HWD + i * 4;
    int l = (int)((i * 4) % HWD);
    float4 v = *(const float4*)(x + base);
    float4 r = *(const float4*)(rn + (size_t)b * HWD + l);
    __half2* o = (__half2*)(y + base);
    o[0] = __floats2half2_rn(v.x * r.x, v.y * r.y);
    o[1] = __floats2half2_rn(v.z * r.z, v.w * r.w);
}

__global__ void stats_kernel(const float* __restrict__ x, float2* __restrict__ st) {
    int bc = blockIdx.x;
    const float* px = x + (size_t)bc * HWD;
    int t = threadIdx.x;
    float s = 0.f, s2 = 0.f;
    for (int i = t; i < HWD; i += 256) { float v = px[i]; s += v; s2 += v * v; }
    __shared__ float r1[256], r2[256];
    r1[t] = s; r2[t] = s2; __syncthreads();
    for (int o = 128; o > 0; o >>= 1) { if (t < o) { r1[t] += r1[t + o]; r2[t] += r2[t + o]; } __syncthreads(); }
    if (t == 0) {
        float mean = r1[0] * (1.0f / HWD);
        float var = (r2[0] - (float)HWD * mean * mean) * (1.0f / (HWD - 1));
        st[bc] = make_float2(mean, rsqrtf(var + 1e-5f));
    }
}

// fused: read x tile once -> xT fp16 [HW,C] and mvn packed [HW,C]
__global__ void fusedT_kernel(const float* __restrict__ x, const float2* __restrict__ st,
                              __half* __restrict__ xT, uint* __restrict__ mvnp) {
    __shared__ float tile[32][33];
    int b = blockIdx.z;
    int c0 = blockIdx.y * 32, h0 = blockIdx.x * 32;
    int tx = threadIdx.x, ty = threadIdx.y;
#pragma unroll
    for (int j = 0; j < 4; j++) {
        int c = c0 + ty + j * 8;
        tile[ty + j * 8][tx] = x[((size_t)b * CDIM + c) * HWD + h0 + tx];
    }
    __syncthreads();
    float2 f = st[b * CDIM + c0 + tx];
#pragma unroll
    for (int j = 0; j < 4; j++) {
        int h = h0 + ty + j * 8;
        float v = tile[tx][ty + j * 8];
        xT[((size_t)b * HWD + h) * CDIM + c0 + tx] = __float2half_rn(v);
        mvnp[((size_t)b * HWD + h) * CDIM + c0 + tx] = packsplit16((v - f.x) * f.y);
    }
}

// reciprocal channel-L2 norm from fp16 transpose [HW,C]
__global__ void rnorm_t_kernel(const __half* __restrict__ xt, float* __restrict__ rn) {
    int row = blockIdx.x * 8 + (threadIdx.x >> 5);
    int lane = threadIdx.x & 31;
    const uint4* p = (const uint4*)(xt + (size_t)row * CDIM) + lane;
    float s = 0.f;
#pragma unroll
    for (int i = 0; i < 2; i++) {
        uint4 v = p[i * 32];
        const __half2* h = (const __half2*)&v;
#pragma unroll
        for (int j = 0; j < 4; j++) { float2 f = __half22float2(h[j]); s += f.x * f.x + f.y * f.y; }
    }
#pragma unroll
    for (int o = 16; o > 0; o >>= 1) s += __shfl_xor_sync(0xffffffffu, s, o);
    if (lane == 0) rn[row] = 1.0f / fmaxf(sqrtf(s), 1e-12f);
}

__global__ void trans512_kernel(const float* __restrict__ x, __half* __restrict__ y) {
    __shared__ float tile[32][33];
    int o0 = blockIdx.y * 32, i0 = blockIdx.x * 32;
    int tx = threadIdx.x, ty = threadIdx.y;
#pragma unroll
    for (int j = 0; j < 4; j++)
        tile[ty + j * 8][tx] = x[(size_t)(o0 + ty + j * 8) * CDIM + i0 + tx];
    __syncthreads();
#pragma unroll
    for (int j = 0; j < 4; j++)
        y[(size_t)(i0 + ty + j * 8) * CDIM + o0 + tx] = __float2half_rn(tile[tx][ty + j * 8]);
}

__global__ void p_kernel(const float* __restrict__ Wg, const float* __restrict__ bf,
                         float* __restrict__ p) {
    int c = blockIdx.x * 128 + threadIdx.x;
    float s = 0.f;
    for (int o = 0; o < CDIM; o++) s += bf[o] * Wg[o * CDIM + c];
    p[c] = s;
}

__global__ void wb_kernel(const float* __restrict__ Wout, const float* __restrict__ bh,
                          float* __restrict__ wb) {
    int c = blockIdx.x * 128 + threadIdx.x;
    float s = 0.f;
    for (int o = 0; o < CDIM; o++) s += Wout[(size_t)c * CDIM + o] * bh[o];
    wb[c] = s;
}

// u[row] = sum_c mvnSt[row,c] * p[c]   (warp per row)
__global__ void u_kernel(const uint* __restrict__ mvnSt, const float* __restrict__ p,
                         float* __restrict__ u) {
    int row = blockIdx.x * 8 + (threadIdx.x >> 5);
    int lane = threadIdx.x & 31;
    const uint* px = mvnSt + (size_t)row * CDIM + lane;
    float s = 0.f;
#pragma unroll
    for (int i = 0; i < 16; i++) s += unpack16(px[i * 32]) * p[lane + i * 32];
#pragma unroll
    for (int o = 16; o > 0; o >>= 1) s += __shfl_xor_sync(0xffffffffu, s, o);
    if (lane == 0) u[row] = s;
}

__global__ void psi_kernel(const float* __restrict__ hmid, const float* __restrict__ W2,
                           const float* __restrict__ b2, float* __restrict__ clampv) {
    int row = blockIdx.x * 4 + (threadIdx.x >> 5);
    int lane = threadIdx.x & 31;
    const float* p = hmid + (size_t)row * HIDD;
    float s = 0.f;
#pragma unroll
    for (int j = lane; j < HIDD; j += 32) s += p[j] * W2[j];
#pragma unroll
    for (int o = 16; o > 0; o >>= 1) s += __shfl_xor_sync(0xffffffffu, s, o);
    if (lane == 0) {
        float psi = 1.f / (1.f + __expf(-(s + b2[0])));
        clampv[row] = psi * 0.5f + 0.4f;
    }
}

// candidate pass over approx fp16 logits (Shat + u): row max + candidate extraction.
// NO tail exp-sum: entries below mx-13 carry <= ~1e-5 of the softmax mass; the
// denominator is rebuilt from exact candidate exps in exact_kernel.
__global__ void cand_kernel(const __half* __restrict__ S, const float* __restrict__ uvec,
                            int* __restrict__ ccnt, int* __restrict__ cidx,
                            float* __restrict__ cmx) {
    size_t row = blockIdx.x;
    int b = (int)(row >> 12);
    const __half* p = S + row * HWD;
    const float* ub = uvec + (size_t)b * HWD;
    __shared__ float buf[HWD];
    __shared__ float red[256];
    int t = threadIdx.x;
    float mx = -1e30f;
    for (int i = t; i < HWD; i += 256) {
        float v = __half2float(p[i]) + ub[i];
        buf[i] = v; mx = fmaxf(mx, v);
    }
    red[t] = mx; __syncthreads();
    for (int o = 128; o > 0; o >>= 1) { if (t < o) red[t] = fmaxf(red[t], red[t + o]); __syncthreads(); }
    mx = red[0]; __syncthreads();
    float thr = mx - 13.0f;
    if (t < 32) {
        int cnt = 0;
        for (int i0 = 0; i0 < HWD; i0 += 32) {
            float v = buf[i0 + t];
            bool q = v > thr;
            uint m = __ballot_sync(0xffffffffu, q);
            if (q) {
                int pos = cnt + __popc(m & ((1u << t) - 1u));
                if (pos < MAXC) cidx[row * MAXC + pos] = i0 + t;
            }
            cnt += __popc(m);
        }
        if (t == 0) {
            ccnt[row] = cnt < MAXC ? cnt : MAXC;
            cmx[row] = mx;
        }
    }
}

// exact pass: recompute candidate logits in fp32 (warp-per-candidate),
// rebuild denominator from exact candidate exps, gate, emit sparse list
__global__ void exact_kernel(const uint* __restrict__ mvnCt, const uint* __restrict__ Tt,
                             const float* __restrict__ uvec, const float* __restrict__ clampv,
                             const int* __restrict__ ccnt, const int* __restrict__ cidx,
                             const float* __restrict__ cmx,
                             int* __restrict__ scnt, int* __restrict__ sidx,
                             float* __restrict__ sval) {
    int row = blockIdx.x;
    int b = row >> 12;
    int t = threadIdx.x;   // 128
    int lane = t & 31, w = t >> 5;
    __shared__ float arow[CDIM];
    __shared__ float elog[MAXC];
    const uint* ar = mvnCt + (size_t)row * CDIM;
#pragma unroll
    for (int q = 0; q < 4; q++) arow[t + 128 * q] = unpack16(ar[t + 128 * q]);
    __syncthreads();
    int cnt = ccnt[row];
    for (int j = w; j < cnt; j += 4) {
        int l = cidx[row * MAXC + j];
        const uint* tc = Tt + (size_t)b * HWD * CDIM + (size_t)l * CDIM;
        float s = 0.f;
#pragma unroll
        for (int q = 0; q < 16; q++) s += arow[lane + 32 * q] * unpack16(tc[lane + 32 * q]);
#pragma unroll
        for (int o = 16; o > 0; o >>= 1) s += __shfl_xor_sync(0xffffffffu, s, o);
        if (lane == 0) elog[j] = s + uvec[(size_t)b * HWD + l];
    }
    __syncthreads();
    if (t == 0) {
        float mx = cmx[row];
        float sum = 0.f;
        for (int j = 0; j < cnt; j++) sum += __expf(elog[j] - mx);
        float inv = 1.0f / sum;
        float cv = clampv[row];
        int k = 0;
        for (int j = 0; j < cnt; j++) {
            float Sv = __expf(elog[j] - mx) * inv;
            float d = Sv - cv;
            if (d > -0.3f && k < MAXE) {
                sidx[row * MAXE + k] = cidx[row * MAXC + j];
                sval[row * MAXE + k] = 1.0f / (1.0f + __expf(-50.0f * d));
                k++;
            }
        }
        scnt[row] = k;
    }
}

// Y[row,c] = sum_j g_j * styleT[l_j, c];  gsum[row] = sum_j g_j
__global__ void gatherY_kernel(const __half* __restrict__ styleT, const int* __restrict__ scnt,
                               const int* __restrict__ sidx, const float* __restrict__ sval,
                               __half* __restrict__ Y, float* __restrict__ gsum) {
    int row = blockIdx.x;
    int b = row >> 12;
    int t = threadIdx.x;
    int c = t * 4;
    const __half* base = styleT + (size_t)b * HWD * CDIM + c;
    float a0 = 0.f, a1 = 0.f, a2 = 0.f, a3 = 0.f;
    float gs = 0.f;
    int cnt = scnt[row];
    for (int j = 0; j < cnt; j++) {
        int l = sidx[row * MAXE + j];
        float g = sval[row * MAXE + j];
        gs += g;
        uint2 v = *(const uint2*)(base + (size_t)l * CDIM);
        float2 f0 = __half22float2(*(__half2*)&v.x);
        float2 f1 = __half22float2(*(__half2*)&v.y);
        a0 += g * f0.x; a1 += g * f0.y; a2 += g * f1.x; a3 += g * f1.y;
    }
    uint2 o;
    *(__half2*)&o.x = __floats2half2_rn(a0, a1);
    *(__half2*)&o.y = __floats2half2_rn(a2, a3);
    *(uint2*)(Y + (size_t)row * CDIM + c) = o;
    if (t == 0) gsum[row] = gs;
}

// ---------------- shared tile movers (packed uint operands) ----------------
template <bool KM>
__device__ __forceinline__ void ldg_tile(const uint* __restrict__ P, int ld, int k0, int c0,
                                         uint4 (&r)[2], int t) {
#pragma unroll
    for (int i = 0; i < 2; i++) {
        int f = i * 256 + t;
        if (KM) {
            int kk = f >> 5, cc = (f & 31) << 2;
            r[i] = *(const uint4*)(P + (size_t)(k0 + kk) * ld + c0 + cc);
        } else {
            int cc = f >> 2, kk = (f & 3) << 2;
            r[i] = *(const uint4*)(P + (size_t)(c0 + cc) * ld + k0 + kk);
        }
    }
}
template <bool KM, bool SPLIT>
__device__ __forceinline__ void sts_tile(unsigned short* hi, unsigned short* lo,
                                         const uint4 (&r)[2], int t) {
#pragma unroll
    for (int i = 0; i < 2; i++) {
        int f = i * 256 + t;
        uint w0 = r[i].x, w1 = r[i].y, w2 = r[i].z, w3 = r[i].w;
        if (KM) {
            int kk = f >> 5, cc = (f & 31) << 2;
            hi[(cc + 0) * 24 + kk] = (unsigned short)w0;
            hi[(cc + 1) * 24 + kk] = (unsigned short)w1;
            hi[(cc + 2) * 24 + kk] = (unsigned short)w2;
            hi[(cc + 3) * 24 + kk] = (unsigned short)w3;
            if (SPLIT) {
                lo[(cc + 0) * 24 + kk] = (unsigned short)(w0 >> 16);
                lo[(cc + 1) * 24 + kk] = (unsigned short)(w1 >> 16);
                lo[(cc + 2) * 24 + kk] = (unsigned short)(w2 >> 16);
                lo[(cc + 3) * 24 + kk] = (unsigned short)(w3 >> 16);
            }
        } else {
            int cc = f >> 2, kk = (f & 3) << 2;
            *(uint*)(hi + cc * 24 + kk)     = prmtb(w0, w1, 0x5410);
            *(uint*)(hi + cc * 24 + kk + 2) = prmtb(w2, w3, 0x5410);
            if (SPLIT) {
                *(uint*)(lo + cc * 24 + kk)     = prmtb(w0, w1, 0x7632);
                *(uint*)(lo + cc * 24 + kk + 2) = prmtb(w2, w3, 0x7632);
            }
        }
    }
}

// ---------------- fp16-split GEMM (fp32 accum; Mm/Tt) ----------------
template <bool A_KM, bool B_NK, bool SPLIT>
__global__ __launch_bounds__(256)
void tc_gemm(const uint* __restrict__ A, const uint* __restrict__ B, float* __restrict__ C,
             int K, int lda, int ldb, int ldc,
             long long sA, long long sB, long long sC,
             const float* __restrict__ bias, long long sBias, int biasMode, int outMode) {
    __shared__ unsigned short AsH[2][128 * 24];
    __shared__ unsigned short BsH[2][128 * 24];
    __shared__ unsigned short AsL[2][SPLIT ? 128 * 24 : 8];
    __shared__ unsigned short BsL[2][SPLIT ? 128 * 24 : 8];
    int bz = blockIdx.z;
    A += sA * bz; B += sB * bz;
    float* Cb = C + sC * bz;
    int bm = blockIdx.y * 128, bn = blockIdx.x * 128;
    int t = threadIdx.x, w = t >> 5, lane = t & 31;
    int wm = (w >> 1) * 32, wn = (w & 1) * 64;
    int g = lane >> 2, tg = lane & 3;

    float acc[2][8][4];
#pragma unroll
    for (int mi = 0; mi < 2; mi++)
#pragma unroll
        for (int ni = 0; ni < 8; ni++)
#pragma unroll
            for (int r = 0; r < 4; r++) acc[mi][ni][r] = 0.f;

    uint4 rA[2], rB[2];
    ldg_tile<A_KM>(A, lda, 0, bm, rA, t);
    ldg_tile<!B_NK>(B, ldb, 0, bn, rB, t);
    sts_tile<A_KM, SPLIT>(AsH[0], AsL[0], rA, t);
    sts_tile<!B_NK, SPLIT>(BsH[0], BsL[0], rB, t);
    __syncthreads();

    int T = K / 16, p = 0;
    for (int kt = 0; kt < T; kt++) {
        if (kt + 1 < T) {
            ldg_tile<A_KM>(A, lda, (kt + 1) * 16, bm, rA, t);
            ldg_tile<!B_NK>(B, ldb, (kt + 1) * 16, bn, rB, t);
        }
        uint aH[2][4], aL[2][4], bH[8][2], bL[8][2];
#pragma unroll
        for (int mi = 0; mi < 2; mi++) {
            const unsigned short* pH = AsH[p] + (wm + mi * 16 + g) * 24 + 2 * tg;
            aH[mi][0] = *(const uint*)(pH);      aH[mi][1] = *(const uint*)(pH + 8 * 24);
            aH[mi][2] = *(const uint*)(pH + 8);  aH[mi][3] = *(const uint*)(pH + 8 * 24 + 8);
            if (SPLIT) {
                const unsigned short* pL = AsL[p] + (wm + mi * 16 + g) * 24 + 2 * tg;
                aL[mi][0] = *(const uint*)(pL);      aL[mi][1] = *(const uint*)(pL + 8 * 24);
                aL[mi][2] = *(const uint*)(pL + 8);  aL[mi][3] = *(const uint*)(pL + 8 * 24 + 8);
            }
        }
#pragma unroll
        for (int ni = 0; ni < 8; ni++) {
            const unsigned short* pH = BsH[p] + (wn + ni * 8 + g) * 24 + 2 * tg;
            bH[ni][0] = *(const uint*)(pH); bH[ni][1] = *(const uint*)(pH + 8);
            if (SPLIT) {
                const unsigned short* pL = BsL[p] + (wn + ni * 8 + g) * 24 + 2 * tg;
                bL[ni][0] = *(const uint*)(pL); bL[ni][1] = *(const uint*)(pL + 8);
            }
        }
#pragma unroll
        for (int mi = 0; mi < 2; mi++)
#pragma unroll
            for (int ni = 0; ni < 8; ni++) {
                mma_hf(acc[mi][ni], aH[mi], bH[ni]);
                if (SPLIT) {
                    mma_hf(acc[mi][ni], aH[mi], bL[ni]);
                    mma_hf(acc[mi][ni], aL[mi], bH[ni]);
                }
            }
        if (kt + 1 < T) {
            p ^= 1;
            sts_tile<A_KM, SPLIT>(AsH[p], AsL[p], rA, t);
            sts_tile<!B_NK, SPLIT>(BsH[p], BsL[p], rB, t);
            __syncthreads();
        }
    }

#pragma unroll
    for (int mi = 0; mi < 2; mi++) {
#pragma unroll
        for (int ni = 0; ni < 8; ni++) {
#pragma unroll
            for (int hf = 0; hf < 2; hf++) {
                int m = bm + wm + mi * 16 + g + hf * 8;
                int n = bn + wn + ni * 8 + 2 * tg;
                float v0 = acc[mi][ni][hf * 2 + 0];
                float v1 = acc[mi][ni][hf * 2 + 1];
                if (biasMode == 1) { float b = bias[m]; v0 += b; v1 += b; }
                if (biasMode == 2) { v0 += bias[sBias * bz + n]; v1 += bias[sBias * bz + n + 1]; }
                if (outMode == 0) {
                    *(float2*)(Cb + (size_t)m * ldc + n) = make_float2(v0, v1);
                } else {
                    uint2 ov = make_uint2(packsplit16(v0), packsplit16(v1));
                    *(uint2*)((uint*)Cb + (size_t)m * ldc + n) = ov;
                }
            }
        }
    }
}

// ---------------- approx S GEMM: hi-planes only, fp16 accum, fp16 out ----------------
__global__ __launch_bounds__(256)
void sgemm_approx(const uint* __restrict__ A, const uint* __restrict__ B, __half* __restrict__ C,
                  int K, int lda, int ldb, int ldc,
                  long long sA, long long sB, long long sC) {
    __shared__ unsigned short AsH[2][128 * 24];
    __shared__ unsigned short BsH[2][128 * 24];
    int bz = blockIdx.z;
    A += sA * bz; B += sB * bz;
    __half* Cb = C + sC * bz;
    int bm = blockIdx.y * 128, bn = blockIdx.x * 128;
    int t = threadIdx.x, w = t >> 5, lane = t & 31;
    int wm = (w >> 1) * 32, wn = (w & 1) * 64;
    int g = lane >> 2, tg = lane & 3;

    uint acc[2][8][2];
#pragma unroll
    for (int mi = 0; mi < 2; mi++)
#pragma unroll
        for (int ni = 0; ni < 8; ni++) { acc[mi][ni][0] = 0u; acc[mi][ni][1] = 0u; }

    uint4 rA[2], rB[2];
    ldg_tile<false>(A, lda, 0, bm, rA, t);
    ldg_tile<false>(B, ldb, 0, bn, rB, t);
    sts_tile<false, false>(AsH[0], nullptr, rA, t);
    sts_tile<false, false>(BsH[0], nullptr, rB, t);
    __syncthreads();

    int T = K / 16, p = 0;
    for (int kt = 0; kt < T; kt++) {
        if (kt + 1 < T) {
            ldg_tile<false>(A, lda, (kt + 1) * 16, bm, rA, t);
            ldg_tile<false>(B, ldb, (kt + 1) * 16, bn, rB, t);
        }
        uint a[2][4], b[8][2];
#pragma unroll
        for (int mi = 0; mi < 2; mi++) {
            const unsigned short* pA = AsH[p] + (wm + mi * 16 + g) * 24 + 2 * tg;
            a[mi][0] = *(const uint*)(pA);      a[mi][1] = *(const uint*)(pA + 8 * 24);
            a[mi][2] = *(const uint*)(pA + 8);  a[mi][3] = *(const uint*)(pA + 8 * 24 + 8);
        }
#pragma unroll
        for (int ni = 0; ni < 8; ni++) {
            const unsigned short* pB = BsH[p] + (wn + ni * 8 + g) * 24 + 2 * tg;
            b[ni][0] = *(const uint*)(pB); b[ni][1] = *(const uint*)(pB + 8);
        }
#pragma unroll
        for (int mi = 0; mi < 2; mi++)
#pragma unroll
            for (int ni = 0; ni < 8; ni++)
                mma_hh(acc[mi][ni], a[mi], b[ni]);
        if (kt + 1 < T) {
            p ^= 1;
            sts_tile<false, false>(AsH[p], nullptr, rA, t);
            sts_tile<false, false>(BsH[p], nullptr, rB, t);
            __syncthreads();
        }
    }

#pragma unroll
    for (int mi = 0; mi < 2; mi++) {
#pragma unroll
        for (int ni = 0; ni < 8; ni++) {
#pragma unroll
            for (int hf = 0; hf < 2; hf++) {
                int m = bm + wm + mi * 16 + g + hf * 8;
                int n = bn + wn + ni * 8 + 2 * tg;
                *(uint*)(Cb + (size_t)m * ldc + n) = acc[mi][ni][hf];
            }
        }
    }
}

// ---------------- plain fp16 GEMM with register prefetch + rank-1 epilogue ----------------
__device__ __forceinline__ uint4 ldg16(const __half* __restrict__ G, size_t ld, int row0, int k0, int t) {
    int row = t >> 1, q = (t & 1) * 8;
    return *(const uint4*)(G + (size_t)(row0 + row) * ld + k0 + q);
}
__device__ __forceinline__ void sts16(__half* __restrict__ Sm, uint4 v, int t) {
    int row = t >> 1, q = (t & 1) * 8;
    *(uint4*)(Sm + row * 24 + q) = v;
}

__global__ __launch_bounds__(256)
void hgemm(const __half* __restrict__ A, const __half* __restrict__ B, float* __restrict__ C,
           int K, size_t lda, size_t ldb, int ldc,
           long long sA, long long sB, long long sC,
           const float* __restrict__ bias, int biasMode,
           const float* __restrict__ scaleM, long long sSM,
           const float* __restrict__ vecM,
           const float* __restrict__ vecN, long long sVN,
           const float* __restrict__ addSrc, long long sAdd,
           int actMode, int outMode) {
    __shared__ __half As[2][128 * 24];
    __shared__ __half Bs[2][128 * 24];
    int bz = blockIdx.z;
    A += sA * bz; B += sB * bz;
    float*  CbF = C + sC * bz;
    __half* CbH = (__half*)C + sC * bz;
    int bm = blockIdx.y * 128, bn = blockIdx.x * 128;
    int t = threadIdx.x, w = t >> 5, lane = t & 31;
    int wm = (w >> 1) * 32, wn = (w & 1) * 64;
    int g = lane >> 2, tg = lane & 3;

    float acc[2][8][4];
#pragma unroll
    for (int mi = 0; mi < 2; mi++)
#pragma unroll
        for (int ni = 0; ni < 8; ni++)
#pragma unroll
            for (int r = 0; r < 4; r++) acc[mi][ni][r] = 0.f;

    uint4 rA = ldg16(A, lda, bm, 0, t);
    uint4 rB = ldg16(B, ldb, bn, 0, t);
    sts16(As[0], rA, t);
    sts16(Bs[0], rB, t);
    __syncthreads();

    int T = K / 16, p = 0;
    for (int kt = 0; kt < T; kt++) {
        if (kt + 1 < T) {
            rA = ldg16(A, lda, bm, (kt + 1) * 16, t);
            rB = ldg16(B, ldb, bn, (kt + 1) * 16, t);
        }
        uint a[2][4], b[8][2];
#pragma unroll
        for (int mi = 0; mi < 2; mi++) {
            const __half* pA = As[p] + (wm + mi * 16 + g) * 24 + 2 * tg;
            a[mi][0] = *(const uint*)(pA);      a[mi][1] = *(const uint*)(pA + 8 * 24);
            a[mi][2] = *(const uint*)(pA + 8);  a[mi][3] = *(const uint*)(pA + 8 * 24 + 8);
        }
#pragma unroll
        for (int ni = 0; ni < 8; ni++) {
            const __half* pB = Bs[p] + (wn + ni * 8 + g) * 24 + 2 * tg;
            b[ni][0] = *(const uint*)(pB); b[ni][1] = *(const uint*)(pB + 8);
        }
#pragma unroll
        for (int mi = 0; mi < 2; mi++)
#pragma unroll
            for (int ni = 0; ni < 8; ni++)
                mma_hf(acc[mi][ni], a[mi], b[ni]);
        if (kt + 1 < T) {
            p ^= 1;
            sts16(As[p], rA, t);
            sts16(Bs[p], rB, t);
            __syncthreads();
        }
    }

#pragma unroll
    for (int mi = 0; mi < 2; mi++) {
#pragma unroll
        for (int ni = 0; ni < 8; ni++) {
#pragma unroll
            for (int hf = 0; hf < 2; hf++) {
                int m = bm + wm + mi * 16 + g + hf * 8;
                int n = bn + wn + ni * 8 + 2 * tg;
                float v0 = acc[mi][ni][hf * 2 + 0];
                float v1 = acc[mi][ni][hf * 2 + 1];
                if (scaleM) { float s = scaleM[sSM * bz + m]; v0 *= s; v1 *= s; }
                if (biasMode == 1) { float b_ = bias[m]; v0 += b_; v1 += b_; }
                if (biasMode == 2) { v0 += bias[n]; v1 += bias[n + 1]; }
                if (vecM) {
                    float vm = vecM[m];
                    v0 += vm * vecN[sVN * bz + n];
                    v1 += vm * vecN[sVN * bz + n + 1];
                }
                if (actMode == 1) {
                    v0 = (v0 > 0.f) ? v0 : 0.2f * v0;
                    v1 = (v1 > 0.f) ? v1 : 0.2f * v1;
                }
                if (addSrc) {
                    v0 += addSrc[sAdd * bz + (size_t)m * ldc + n];
                    v1 += addSrc[sAdd * bz + (size_t)m * ldc + n + 1];
                }
                if (outMode == 0) {
                    *(float2*)(CbF + (size_t)m * ldc + n) = make_float2(v0, v1);
                } else {
                    *(__half2*)(CbH + (size_t)m * ldc + n) = __floats2half2_rn(v0, v1);
                }
            }
        }
    }
}

// ---------------- host launcher ----------------
extern "C" void kernel_launch(void* const* d_in, const int* in_sizes, int n_in,
                              void* d_out, int out_size) {
    const float* content = (const float*)d_in[0];
    const float* style   = (const float*)d_in[1];
    const float* Wf   = (const float*)d_in[2];
    const float* bf   = (const float*)d_in[3];
    const float* Wg   = (const float*)d_in[4];
    const float* bg   = (const float*)d_in[5];
    const float* Wh   = (const float*)d_in[6];
    const float* bh   = (const float*)d_in[7];
    const float* Wout = (const float*)d_in[8];
    const float* bout = (const float*)d_in[9];
    const float* W1   = (const float*)d_in[10];
    const float* b1   = (const float*)d_in[11];
    const float* W2   = (const float*)d_in[12];
    const float* b2   = (const float*)d_in[13];
    float* out = (float*)d_out;

    uint *mvnCt, *mvnSt, *Tt, *Mm, *Wfs, *Wgs;
    __half *S, *styleT, *contentT, *styleR, *Yh, *T1t, *WhT, *Wos, *Wouth, *W1h;
    float *hmid, *rnC, *rnS, *clampv, *sval, *pv, *uv, *wbv, *gsum, *cmx;
    float2 *stC, *stS;
    int *scnt, *sidx, *ccnt, *cidx;
    cudaGetSymbolAddress((void**)&mvnCt, g_mvnC_t);
    cudaGetSymbolAddress((void**)&mvnSt, g_mvnS_t);
    cudaGetSymbolAddress((void**)&Tt, g_Tt);
    cudaGetSymbolAddress((void**)&Mm, g_Mm);
    cudaGetSymbolAddress((void**)&S, g_S);
    cudaGetSymbolAddress((void**)&styleT, g_styleT);
    cudaGetSymbolAddress((void**)&contentT, g_contentT);
    cudaGetSymbolAddress((void**)&styleR, g_styleR);
    cudaGetSymbolAddress((void**)&Yh, g_Y);
    cudaGetSymbolAddress((void**)&T1t, g_T1t);
    cudaGetSymbolAddress((void**)&hmid, g_hmid);
    cudaGetSymbolAddress((void**)&rnC, g_rnC);
    cudaGetSymbolAddress((void**)&rnS, g_rnS);
    cudaGetSymbolAddress((void**)&clampv, g_clamp);
    cudaGetSymbolAddress((void**)&pv, g_p);
    cudaGetSymbolAddress((void**)&uv, g_u);
    cudaGetSymbolAddress((void**)&wbv, g_wb);
    cudaGetSymbolAddress((void**)&gsum, g_gsum);
    cudaGetSymbolAddress((void**)&scnt, g_scnt);
    cudaGetSymbolAddress((void**)&sidx, g_sidx);
    cudaGetSymbolAddress((void**)&sval, g_sval);
    cudaGetSymbolAddress((void**)&ccnt, g_ccnt);
    cudaGetSymbolAddress((void**)&cidx, g_cidx);
    cudaGetSymbolAddress((void**)&cmx, g_cmx);
    cudaGetSymbolAddress((void**)&stC, g_statC);
    cudaGetSymbolAddress((void**)&stS, g_statS);
    cudaGetSymbolAddress((void**)&Wfs, g_Wfs);
    cudaGetSymbolAddress((void**)&Wgs, g_Wgs);
    cudaGetSymbolAddress((void**)&WhT, g_WhT);
    cudaGetSymbolAddress((void**)&Wos, g_Wos);
    cudaGetSymbolAddress((void**)&Wouth, g_Wouth);
    cudaGetSymbolAddress((void**)&W1h, g_W1h);

    const long long CS  = (long long)CDIM * HWD;
    const long long CT  = (long long)HWD * CDIM;
    const long long SS  = (long long)HWD * HWD;
    const long long HSC = (long long)HIDD * CDIM;
    const long long HM  = (long long)HWD * HIDD;

    // 0) weights
    split16_kernel<<<CDIM * CDIM / 1024, 256>>>((const float4*)Wf, (uint4*)Wfs);
    split16_kernel<<<CDIM * CDIM / 1024, 256>>>((const float4*)Wg, (uint4*)Wgs);
    tohalf_kernel<<<CDIM * CDIM / 1024, 256>>>((const float4*)Wout, Wos);
    tohalf_kernel<<<HIDD * HWD / 1024, 256>>>((const float4*)W1, W1h);
    trans512_kernel<<<dim3(16, 16), dim3(32, 8)>>>(Wh, WhT);
    wb_kernel<<<CDIM / 128, 128>>>(Wout, bh, wbv);
    dim3 gW(CDIM / 128, CDIM / 128, 1);
    hgemm<<<gW, 256>>>(Wos, WhT, (float*)Wouth, CDIM, CDIM, CDIM, CDIM,
        0, 0, 0, nullptr, 0, nullptr, 0, nullptr, nullptr, 0, nullptr, 0, 0, 1);

    // 1) stats + fused transpose/mvn + norms
    stats_kernel<<<BDIM * CDIM, 256>>>(content, stC);
    stats_kernel<<<BDIM * CDIM, 256>>>(style, stS);
    dim3 gT(HWD / 32, CDIM / 32, BDIM), bT(32, 8);
    fusedT_kernel<<<gT, bT>>>(content, stC, contentT, mvnCt);
    fusedT_kernel<<<gT, bT>>>(style, stS, styleT, mvnSt);
    rnorm_t_kernel<<<BDIM * HWD / 8, 256>>>(contentT, rnC);
    rnorm_t_kernel<<<BDIM * HWD / 8, 256>>>(styleT, rnS);
    scalehalf_kernel<<<dim3(CDIM * HWD / 1024, BDIM), 256>>>(style, rnS, styleR);
    p_kernel<<<CDIM / 128, 128>>>(Wg, bf, pv);
    u_kernel<<<BDIM * HWD / 8, 256>>>(mvnSt, pv, uv);

    // 2) logit chain: Mm (split), Tt (split), approx S (1-pass hi, fp16 accum, fp16 out)
    dim3 gM(CDIM / 128, CDIM / 128, 1);
    tc_gemm<true, false, true><<<gM, 256>>>(Wfs, Wgs, (float*)Mm, CDIM, CDIM, CDIM, CDIM,
        0, 0, 0, nullptr, 0, 0, 1);
    dim3 gTt(CDIM / 128, HWD / 128, BDIM);
    tc_gemm<false, true, true><<<gTt, 256>>>(mvnSt, Mm, (float*)Tt, CDIM, CDIM, CDIM, CDIM,
        CT, 0, CT, nullptr, 0, 0, 1);
    dim3 gBig(HWD / 128, HWD / 128, BDIM);
    sgemm_approx<<<gBig, 256>>>(mvnCt, Tt, S, CDIM, CDIM, CDIM, HWD, CT, CT, SS);

    // 3) fused clamp path
    dim3 gT1(CDIM / 128, HIDD / 128, BDIM);
    hgemm<<<gT1, 256>>>(W1h, styleR, (float*)T1t, HWD, HWD, HWD, CDIM,
        0, CS, HSC, nullptr, 0, nullptr, 0, nullptr, nullptr, 0, nullptr, 0, 0, 1);
    dim3 gT2(HIDD / 128, HWD / 128, BDIM);
    hgemm<<<gT2, 256>>>(contentT, T1t, hmid, CDIM, CDIM, CDIM, HIDD,
        CT, HSC, HM, b1, 2, rnC, HWD, nullptr, nullptr, 0, nullptr, 0, 1, 0);
    psi_kernel<<<BDIM * HWD / 4, 128>>>(hmid, W2, b2, clampv);

    // 4) candidates from approx fp16 logits (no tail sum), exact recompute + gate
    cand_kernel<<<BDIM * HWD, 256>>>(S, uv, ccnt, cidx, cmx);
    exact_kernel<<<BDIM * HWD, 128>>>(mvnCt, Tt, uv, clampv, ccnt, cidx, cmx,
                                      scnt, sidx, sval);

    // 5) sparse gather + fused output GEMM
    gatherY_kernel<<<BDIM * HWD, 128>>>(styleT, scnt, sidx, sval, Yh, gsum);
    dim3 gF(HWD / 128, CDIM / 128, BDIM);
    hgemm<<<gF, 256>>>(Wouth, Yh, out, CDIM, CDIM, CDIM, HWD,
        0, CT, CS, bout, 1, nullptr, 0, wbv, gsum, HWD, content, CS, 0, 0);
}